// round 7
// baseline (speedup 1.0000x reference)
#include <cuda_runtime.h>
#include <math.h>

#define B_ 4
#define T_ 256
#define N_ 48
#define F_ 4
#define H_ 64
#define K_ 4
#define E_ 192
#define LH_ 512
#define C_ 8
#define G_ (B_*T_)     // 1024
#define KH_ (K_*H_)    // 256
#define KHP_ (KH_+1)
#define NH_ (N_*H_)    // 3072
#define G4_ (4*LH_)    // 2048
#define NEG_SLOPE 0.2f

#define LCTAS 32
#define LTHR 256
#define JPC 16         // h-indices per LSTM CTA (x4 gates = 64 rows)
#define WPAD 516       // 512+4 floats: 16B-aligned rows, bank-spread
#define HCH 132        // staged-h chunk stride (128+4): distinct banks per chunk

// ---------------- scratch ----------------------------------------------------
__device__ float g_h1[G_*N_*KH_];
__device__ float g_seq[G_*NH_];
__device__ float g_xw[G_*G4_];
__device__ float g_hbuf[2][B_][LH_];
__device__ int   g_coff[N_+1];
__device__ int   g_ceid[E_];
__device__ unsigned g_cnt;
__device__ volatile unsigned g_gen;
__device__ unsigned g_scnt[T_];

// ---------------- deterministic CSR build ------------------------------------
__global__ void build_csr_kernel(const int* __restrict__ ei)
{
    __shared__ int sdst[E_];
    __shared__ int sdeg[N_];
    __shared__ int soff[N_+1];
    int tid = threadIdx.x;
    for (int e = tid; e < E_; e += blockDim.x) sdst[e] = ei[E_ + e];
    __syncthreads();
    for (int n = tid; n < N_; n += blockDim.x) {
        int d = 0;
        for (int e = 0; e < E_; e++) d += (sdst[e] == n);
        sdeg[n] = d;
    }
    __syncthreads();
    if (tid == 0) {
        int acc = 0;
        for (int n = 0; n < N_; n++) { soff[n] = acc; acc += sdeg[n]; }
        soff[N_] = acc;
    }
    __syncthreads();
    for (int n = tid; n < N_; n += blockDim.x) {
        int p = soff[n];
        for (int e = 0; e < E_; e++) if (sdst[e] == n) g_ceid[p++] = e;
    }
    for (int n = tid; n <= N_; n += blockDim.x) g_coff[n] = soff[n];
}

// ---------------- GAT layer 1 ------------------------------------------------
__global__ __launch_bounds__(256) void gat1_kernel(
    const float* __restrict__ x, const int* __restrict__ ei,
    const float* __restrict__ Wl, const float* __restrict__ Wr,
    const float* __restrict__ att, const float* __restrict__ bias)
{
    extern __shared__ float sm[];
    float* xl   = sm;
    float* xr   = xl + N_*KHP_;
    float* wl   = xr + N_*KHP_;
    float* wr   = wl + F_*KH_;
    float* satt = wr + F_*KH_;
    float* sb   = satt + KH_;
    float* sx   = sb + KH_;
    float* se   = sx + N_*F_;
    int* ssrc = (int*)(se + E_*K_);
    int* sdst = ssrc + E_;
    int* soff = sdst + E_;
    int* seid = soff + (N_+1);

    int g = blockIdx.x;
    int tid = threadIdx.x;

    for (int i = tid; i < F_*KH_; i += 256) { wl[i] = Wl[i]; wr[i] = Wr[i]; }
    satt[tid] = att[tid];
    sb[tid] = bias[tid];
    for (int i = tid; i < N_*F_; i += 256) sx[i] = x[(size_t)g*N_*F_ + i];
    for (int i = tid; i < E_; i += 256) { ssrc[i] = ei[i]; sdst[i] = ei[E_+i]; seid[i] = g_ceid[i]; }
    for (int i = tid; i <= N_; i += 256) soff[i] = g_coff[i];
    __syncthreads();

    const int o = tid;
    for (int n = 0; n < N_; n++) {
        float al = 0.f, ar = 0.f;
        #pragma unroll
        for (int f = 0; f < F_; f++) {
            float xv = sx[n*F_ + f];
            al += xv * wl[f*KH_ + o];
            ar += xv * wr[f*KH_ + o];
        }
        xl[n*KHP_ + o] = al;
        xr[n*KHP_ + o] = ar;
    }
    __syncthreads();

    for (int idx = tid; idx < E_*K_; idx += 256) {
        int e = idx >> 2, k = idx & 3;
        const float* pl = xl + ssrc[e]*KHP_ + k*H_;
        const float* pr = xr + sdst[e]*KHP_ + k*H_;
        const float* pa = satt + k*H_;
        float acc = 0.f;
        #pragma unroll 8
        for (int h = 0; h < H_; h++) {
            float v = pl[h] + pr[h];
            v = v > 0.f ? v : NEG_SLOPE * v;
            acc += v * pa[h];
        }
        se[idx] = acc;
    }
    __syncthreads();

    for (int idx = tid; idx < N_*K_; idx += 256) {
        int n = idx >> 2, k = idx & 3;
        int a0 = soff[n], a1 = soff[n+1];
        float mx = -1e30f;
        for (int a = a0; a < a1; a++) mx = fmaxf(mx, se[seid[a]*K_ + k]);
        float s = 0.f;
        for (int a = a0; a < a1; a++) s += expf(se[seid[a]*K_ + k] - mx);
        float inv = 1.f / (s + 1e-16f);
        for (int a = a0; a < a1; a++) {
            int j = seid[a]*K_ + k;
            se[j] = expf(se[j] - mx) * inv;
        }
    }
    __syncthreads();

    int k = o >> 6;
    float* outp = g_h1 + (size_t)g*N_*KH_;
    for (int n = 0; n < N_; n++) {
        int a0 = soff[n], a1 = soff[n+1];
        float acc = 0.f;
        for (int a = a0; a < a1; a++) {
            int e = seid[a];
            acc += se[e*K_ + k] * xl[ssrc[e]*KHP_ + o];
        }
        outp[n*KH_ + o] = fmaxf(acc + sb[o], 0.f);
    }
}

// ---------------- GAT layer 2 (fused fp32, proven) ----------------------------
__global__ __launch_bounds__(256) void gat2_kernel(
    const int* __restrict__ ei,
    const float* __restrict__ Wl, const float* __restrict__ Wr,
    const float* __restrict__ att, const float* __restrict__ bias)
{
    extern __shared__ float sm[];
    float* sh_in = sm;
    float* xl    = sh_in + N_*KH_;
    float* xr    = xl + N_*KHP_;
    float* satt  = xr + N_*KHP_;
    float* sb    = satt + KH_;
    float* se    = sb + H_;
    int* ssrc = (int*)(se + E_*K_);
    int* sdst = ssrc + E_;
    int* soff = sdst + E_;
    int* seid = soff + (N_+1);

    int g = blockIdx.x;
    int tid = threadIdx.x;

    const float* h1p = g_h1 + (size_t)g*N_*KH_;
    for (int i = tid; i < N_*KH_; i += 256) sh_in[i] = h1p[i];
    satt[tid] = att[tid];
    if (tid < H_) sb[tid] = bias[tid];
    for (int i = tid; i < E_; i += 256) { ssrc[i] = ei[i]; sdst[i] = ei[E_+i]; seid[i] = g_ceid[i]; }
    for (int i = tid; i <= N_; i += 256) soff[i] = g_coff[i];
    __syncthreads();

    const int o = tid;
    {
        float acc[N_];
        #pragma unroll
        for (int n = 0; n < N_; n++) acc[n] = 0.f;
        #pragma unroll 2
        for (int i = 0; i < KH_; i++) {
            float w = Wl[i*KH_ + o];
            #pragma unroll
            for (int n = 0; n < N_; n++) acc[n] += sh_in[n*KH_ + i] * w;
        }
        #pragma unroll
        for (int n = 0; n < N_; n++) xl[n*KHP_ + o] = acc[n];
    }
    {
        float acc[N_];
        #pragma unroll
        for (int n = 0; n < N_; n++) acc[n] = 0.f;
        #pragma unroll 2
        for (int i = 0; i < KH_; i++) {
            float w = Wr[i*KH_ + o];
            #pragma unroll
            for (int n = 0; n < N_; n++) acc[n] += sh_in[n*KH_ + i] * w;
        }
        #pragma unroll
        for (int n = 0; n < N_; n++) xr[n*KHP_ + o] = acc[n];
    }
    __syncthreads();

    for (int idx = tid; idx < E_*K_; idx += 256) {
        int e = idx >> 2, k = idx & 3;
        const float* pl = xl + ssrc[e]*KHP_ + k*H_;
        const float* pr = xr + sdst[e]*KHP_ + k*H_;
        const float* pa = satt + k*H_;
        float acc = 0.f;
        #pragma unroll 8
        for (int h = 0; h < H_; h++) {
            float v = pl[h] + pr[h];
            v = v > 0.f ? v : NEG_SLOPE * v;
            acc += v * pa[h];
        }
        se[idx] = acc;
    }
    __syncthreads();

    for (int idx = tid; idx < N_*K_; idx += 256) {
        int n = idx >> 2, k = idx & 3;
        int a0 = soff[n], a1 = soff[n+1];
        float mx = -1e30f;
        for (int a = a0; a < a1; a++) mx = fmaxf(mx, se[seid[a]*K_ + k]);
        float s = 0.f;
        for (int a = a0; a < a1; a++) s += expf(se[seid[a]*K_ + k] - mx);
        float inv = 1.f / (s + 1e-16f);
        for (int a = a0; a < a1; a++) {
            int j = seid[a]*K_ + k;
            se[j] = expf(se[j] - mx) * inv;
        }
    }
    __syncthreads();

    for (int idx = tid; idx < N_*H_; idx += 256) {
        int n = idx >> 6, h = idx & 63;
        int a0 = soff[n], a1 = soff[n+1];
        float acc = 0.f;
        for (int a = a0; a < a1; a++) {
            int e = seid[a]; int s = ssrc[e];
            #pragma unroll
            for (int k2 = 0; k2 < K_; k2++)
                acc += se[e*K_ + k2] * xl[s*KHP_ + k2*H_ + h];
        }
        float v = acc * 0.25f + sb[h];
        g_seq[(size_t)g*NH_ + n*H_ + h] = fmaxf(v, 0.f);
    }
}

// ---------------- xw GEMM (proven 64x64x32 fp32) ------------------------------
#define BM 64
#define BN 64
#define BK 32
#define BMP (BM+4)
#define BNP (BN+4)
__global__ __launch_bounds__(256) void xw_gemm_kernel(
    const float* __restrict__ W_ih,
    const float* __restrict__ b_ih, const float* __restrict__ b_hh)
{
    __shared__ float As[BK][BMP];
    __shared__ float Bs[BK][BNP];
    int bn = blockIdx.x, bm = blockIdx.y;
    int tid = threadIdx.x;
    int tx = tid & 15, ty = tid >> 4;
    float acc[4][4] = {};
    const float* A0 = g_seq + (size_t)(bm*BM)*NH_;
    const float* B0 = W_ih + (size_t)(bn*BN)*NH_;
    int lr = tid >> 3;
    int lc = (tid & 7) * 4;

    for (int k0 = 0; k0 < NH_; k0 += BK) {
        #pragma unroll
        for (int half = 0; half < 2; half++) {
            int r = lr + half*32;
            float4 a4 = *(const float4*)&A0[(size_t)r*NH_ + k0 + lc];
            As[lc+0][r] = a4.x; As[lc+1][r] = a4.y;
            As[lc+2][r] = a4.z; As[lc+3][r] = a4.w;
            float4 b4 = *(const float4*)&B0[(size_t)r*NH_ + k0 + lc];
            Bs[lc+0][r] = b4.x; Bs[lc+1][r] = b4.y;
            Bs[lc+2][r] = b4.z; Bs[lc+3][r] = b4.w;
        }
        __syncthreads();
        #pragma unroll
        for (int k = 0; k < BK; k++) {
            float4 av = *(const float4*)&As[k][ty*4];
            float4 bv = *(const float4*)&Bs[k][tx*4];
            float a[4] = {av.x, av.y, av.z, av.w};
            float b[4] = {bv.x, bv.y, bv.z, bv.w};
            #pragma unroll
            for (int i = 0; i < 4; i++)
                #pragma unroll
                for (int j = 0; j < 4; j++)
                    acc[i][j] += a[i] * b[j];
        }
        __syncthreads();
    }
    #pragma unroll
    for (int i = 0; i < 4; i++) {
        int r = bm*BM + ty*4 + i;
        int c = bn*BN + tx*4;
        float4 o;
        o.x = acc[i][0] + b_ih[c+0] + b_hh[c+0];
        o.y = acc[i][1] + b_ih[c+1] + b_hh[c+1];
        o.z = acc[i][2] + b_ih[c+2] + b_hh[c+2];
        o.w = acc[i][3] + b_ih[c+3] + b_hh[c+3];
        *(float4*)&g_xw[(size_t)r*G4_ + c] = o;
    }
}

// ---------------- persistent LSTM: batch-amortized W reads --------------------
__device__ __forceinline__ float sigm(float x) { return 1.f / (1.f + expf(-x)); }

#define FMA2(acc, a, b) \
    asm("fma.rn.f32x2 %0, %1, %2, %0;" : "+l"(acc) : "l"(a), "l"(b))

__device__ __forceinline__ float unpack_sum(unsigned long long v)
{
    unsigned lo, hi;
    asm("mov.b64 {%0, %1}, %2;" : "=r"(lo), "=r"(hi) : "l"(v));
    return __uint_as_float(lo) + __uint_as_float(hi);
}

__device__ __forceinline__ void init_barrier()
{
    __syncthreads();
    if (threadIdx.x == 0) {
        unsigned my = g_gen;
        __threadfence();
        if (atomicAdd(&g_cnt, 1u) == LCTAS - 1) {
            atomicExch(&g_cnt, 0u);
            __threadfence();
            atomicAdd((unsigned*)&g_gen, 1u);
        } else {
            while (g_gen == my) { }
        }
    }
    __syncthreads();
}

__global__ __launch_bounds__(LTHR) void lstm_kernel(const float* __restrict__ W_hh)
{
    extern __shared__ float sm[];
    float* sw   = sm;                    // 64 rows x WPAD  (132 KB)
    float* shh  = sw + 64*WPAD;          // staged h: [b][chunk] 16 x HCH
    float* sval = shh + 16*HCH;          // 64 rows x 4 batches

    int tid = threadIdx.x, blk = blockIdx.x;
    int j0 = blk * JPC;

    // W_hh slice: smem row gate*16+jj <- W_hh row gate*LH_+j0+jj
    for (int idx = tid; idx < 64*(LH_/4); idx += LTHR) {
        int row = idx >> 7, iv = idx & 127;
        int gate = row >> 4, jj = row & 15;
        float4 v = *(const float4*)&W_hh[(size_t)(gate*LH_ + j0 + jj)*LH_ + iv*4];
        *(float4*)&sw[row*WPAD + iv*4] = v;
    }
    if (tid < T_/LCTAS) g_scnt[blk*(T_/LCTAS) + tid] = 0;
    for (int idx = tid; idx < B_*JPC; idx += LTHR) {
        int b = idx >> 4, jj = idx & 15;
        g_hbuf[0][b][j0 + jj] = 0.f;
    }
    __threadfence();
    init_barrier();

    // compute map: warp w -> rows 8w..8w+7; lane: r=lane>>2 (row), cc=lane&3 (chunk)
    const int w = tid >> 5, lane = tid & 31;
    const int r = lane >> 2, cc = lane & 3;
    const int row = w*8 + r;                 // gate = row>>4, jj = row&15
    const ulonglong2* wv = (const ulonglong2*)(sw + row*WPAD + cc*128);
    const ulonglong2* hp0 = (const ulonglong2*)(shh + (0*4 + cc)*HCH);
    const ulonglong2* hp1 = (const ulonglong2*)(shh + (1*4 + cc)*HCH);
    const ulonglong2* hp2 = (const ulonglong2*)(shh + (2*4 + cc)*HCH);
    const ulonglong2* hp3 = (const ulonglong2*)(shh + (3*4 + cc)*HCH);

    // pointwise map (tid<64): jj2 = tid>>2, bb = tid&3; persistent cell state
    const int jj2 = tid >> 2, bb = tid & 3;
    float cstate = 0.f;
    float x4[4];
    if (tid < 64) {
        #pragma unroll
        for (int g = 0; g < 4; g++)
            x4[g] = __ldcg(&g_xw[(size_t)(bb*T_ + 0)*G4_ + g*LH_ + j0 + jj2]);
    }

    for (int t = 0; t < T_; t++) {
        int p = t & 1;
        // stage h_prev: 2048 floats = 512 float4; layout shh[b*4+c][i]
        {
            float4 hv0 = __ldcg(((const float4*)&g_hbuf[p][0][0]) + tid);
            float4 hv1 = __ldcg(((const float4*)&g_hbuf[p][0][0]) + tid + 256);
            int v0 = tid,      b0 = v0 >> 7, w0 = v0 & 127;
            int v1 = tid + 256, b1 = v1 >> 7, w1 = v1 & 127;
            *(float4*)&shh[(b0*4 + (w0 >> 5))*HCH + (w0 & 31)*4] = hv0;
            *(float4*)&shh[(b1*4 + (w1 >> 5))*HCH + (w1 & 31)*4] = hv1;
        }
        __syncthreads();

        // dot chunk: W[row][cc*128..+128) x h[b][same] for all 4 b, f32x2 packed
        unsigned long long a0 = 0ull, a1 = 0ull, a2 = 0ull, a3 = 0ull;
        #pragma unroll 4
        for (int i = 0; i < 32; i++) {
            ulonglong2 wq = wv[i];
            ulonglong2 q0 = hp0[i];
            ulonglong2 q1 = hp1[i];
            ulonglong2 q2 = hp2[i];
            ulonglong2 q3 = hp3[i];
            FMA2(a0, wq.x, q0.x); FMA2(a0, wq.y, q0.y);
            FMA2(a1, wq.x, q1.x); FMA2(a1, wq.y, q1.y);
            FMA2(a2, wq.x, q2.x); FMA2(a2, wq.y, q2.y);
            FMA2(a3, wq.x, q3.x); FMA2(a3, wq.y, q3.y);
        }
        float s0 = unpack_sum(a0);
        float s1 = unpack_sum(a1);
        float s2 = unpack_sum(a2);
        float s3 = unpack_sum(a3);
        // reduce over the 4 chunk-lanes (lanes r*4+cc, xor 1 then 2)
        s0 += __shfl_xor_sync(0xffffffffu, s0, 1); s0 += __shfl_xor_sync(0xffffffffu, s0, 2);
        s1 += __shfl_xor_sync(0xffffffffu, s1, 1); s1 += __shfl_xor_sync(0xffffffffu, s1, 2);
        s2 += __shfl_xor_sync(0xffffffffu, s2, 1); s2 += __shfl_xor_sync(0xffffffffu, s2, 2);
        s3 += __shfl_xor_sync(0xffffffffu, s3, 1); s3 += __shfl_xor_sync(0xffffffffu, s3, 2);
        if (cc == 0) {
            sval[row*4 + 0] = s0;
            sval[row*4 + 1] = s1;
            sval[row*4 + 2] = s2;
            sval[row*4 + 3] = s3;
        }
        __syncthreads();

        // pointwise: thread (jj2, bb) combines 4 gates
        if (tid < 64) {
            float gi = sval[(0*16 + jj2)*4 + bb] + x4[0];
            float gf = sval[(1*16 + jj2)*4 + bb] + x4[1];
            float gg = sval[(2*16 + jj2)*4 + bb] + x4[2];
            float go = sval[(3*16 + jj2)*4 + bb] + x4[3];
            cstate = sigm(gf)*cstate + sigm(gi)*tanhf(gg);
            float h = sigm(go)*tanhf(cstate);
            g_hbuf[p ^ 1][bb][j0 + jj2] = h;
        }
        __syncthreads();                 // h stores + sval reads complete

        if (t < T_-1) {
            // prefetch next step's x (overlaps barrier)
            if (tid < 64) {
                #pragma unroll
                for (int g = 0; g < 4; g++)
                    x4[g] = __ldcg(&g_xw[(size_t)(bb*T_ + t + 1)*G4_ + g*LH_ + j0 + jj2]);
            }
            unsigned* cp = &g_scnt[t];
            if (tid == 0)
                asm volatile("red.release.gpu.global.add.u32 [%0], %1;"
                             :: "l"(cp), "r"(1u) : "memory");
            unsigned v;
            do {
                asm volatile("ld.acquire.gpu.global.u32 %0, [%1];"
                             : "=r"(v) : "l"(cp) : "memory");
            } while (v < LCTAS);
        }
    }
}

// ---------------- final fc -----------------------------------------------------
__global__ void fc_kernel(const float* __restrict__ fc_w,
                          const float* __restrict__ fc_b,
                          float* __restrict__ out)
{
    int tid = threadIdx.x;
    if (tid < B_*C_) {
        int b = tid >> 3, c = tid & 7;
        const float* h = g_hbuf[0][b];   // T even -> final h in buffer 0
        const float* w = fc_w + c*LH_;
        float acc = 0.f;
        for (int j = 0; j < LH_; j++) acc += h[j] * w[j];
        out[b*C_ + c] = acc + fc_b[c];
    }
}

// ---------------- launch -------------------------------------------------------
extern "C" void kernel_launch(void* const* d_in, const int* in_sizes, int n_in,
                              void* d_out, int out_size)
{
    (void)in_sizes; (void)n_in; (void)out_size;
    const float* x    = (const float*)d_in[0];
    const int*   ei   = (const int*)d_in[1];
    const float* Wl1  = (const float*)d_in[2];
    const float* Wr1  = (const float*)d_in[3];
    const float* att1 = (const float*)d_in[4];
    const float* b1   = (const float*)d_in[5];
    const float* Wl2  = (const float*)d_in[6];
    const float* Wr2  = (const float*)d_in[7];
    const float* att2 = (const float*)d_in[8];
    const float* b2   = (const float*)d_in[9];
    const float* W_ih = (const float*)d_in[10];
    const float* W_hh = (const float*)d_in[11];
    const float* b_ih = (const float*)d_in[12];
    const float* b_hh = (const float*)d_in[13];
    const float* fc_w = (const float*)d_in[14];
    const float* fc_b = (const float*)d_in[15];
    float* out = (float*)d_out;

    const size_t sm1 = (size_t)(2*N_*KHP_ + 2*F_*KH_ + 2*KH_ + N_*F_ + E_*K_) * 4
                     + (size_t)(2*E_ + (N_+1) + E_) * 4;
    const size_t sm2 = (size_t)(N_*KH_ + 2*N_*KHP_ + KH_ + H_ + E_*K_) * 4
                     + (size_t)(2*E_ + (N_+1) + E_) * 4;
    const size_t sml = (size_t)(64*WPAD + 16*HCH + 64*4) * 4;

    cudaFuncSetAttribute(gat1_kernel, cudaFuncAttributeMaxDynamicSharedMemorySize, (int)sm1);
    cudaFuncSetAttribute(gat2_kernel, cudaFuncAttributeMaxDynamicSharedMemorySize, (int)sm2);
    cudaFuncSetAttribute(lstm_kernel, cudaFuncAttributeMaxDynamicSharedMemorySize, (int)sml);

    build_csr_kernel<<<1, 64>>>(ei);
    gat1_kernel<<<G_, 256, sm1>>>(x, ei, Wl1, Wr1, att1, b1);
    gat2_kernel<<<G_, 256, sm2>>>(ei, Wl2, Wr2, att2, b2);
    dim3 gx(G4_/BN, G_/BM);
    xw_gemm_kernel<<<gx, 256>>>(W_ih, b_ih, b_hh);
    lstm_kernel<<<LCTAS, LTHR, sml>>>(W_hh);
    fc_kernel<<<1, 32>>>(fc_w, fc_b, out);
}

// round 8
// speedup vs baseline: 1.0900x; 1.0900x over previous
#include <cuda_runtime.h>
#include <math.h>
#include <mma.h>
using namespace nvcuda;

#define B_ 4
#define T_ 256
#define N_ 48
#define F_ 4
#define H_ 64
#define K_ 4
#define E_ 192
#define LH_ 512
#define C_ 8
#define G_ (B_*T_)     // 1024
#define KH_ (K_*H_)    // 256
#define KHP_ (KH_+1)
#define NH_ (N_*H_)    // 3072
#define G4_ (4*LH_)    // 2048
#define NEG_SLOPE 0.2f

#define LCTAS 64
#define LTHR 128
#define JPC 8
#define WPAD 516

// ---------------- scratch ----------------------------------------------------
__device__ float g_h1[G_*N_*KH_];
__device__ float g_seq[G_*NH_];
__device__ float g_xw[G_*G4_];
__device__ float g_hbuf[2][B_][LH_];
__device__ int   g_coff[N_+1];
__device__ int   g_ceid[E_];
__device__ unsigned g_cnt;
__device__ volatile unsigned g_gen;
__device__ unsigned g_scnt[T_];

// ---------------- deterministic CSR build ------------------------------------
__global__ void build_csr_kernel(const int* __restrict__ ei)
{
    __shared__ int sdst[E_];
    __shared__ int sdeg[N_];
    __shared__ int soff[N_+1];
    int tid = threadIdx.x;
    for (int e = tid; e < E_; e += blockDim.x) sdst[e] = ei[E_ + e];
    __syncthreads();
    for (int n = tid; n < N_; n += blockDim.x) {
        int d = 0;
        for (int e = 0; e < E_; e++) d += (sdst[e] == n);
        sdeg[n] = d;
    }
    __syncthreads();
    if (tid == 0) {
        int acc = 0;
        for (int n = 0; n < N_; n++) { soff[n] = acc; acc += sdeg[n]; }
        soff[N_] = acc;
    }
    __syncthreads();
    for (int n = tid; n < N_; n += blockDim.x) {
        int p = soff[n];
        for (int e = 0; e < E_; e++) if (sdst[e] == n) g_ceid[p++] = e;
    }
    for (int n = tid; n <= N_; n += blockDim.x) g_coff[n] = soff[n];
}

// ---------------- GAT layer 1 ------------------------------------------------
__global__ __launch_bounds__(256) void gat1_kernel(
    const float* __restrict__ x, const int* __restrict__ ei,
    const float* __restrict__ Wl, const float* __restrict__ Wr,
    const float* __restrict__ att, const float* __restrict__ bias)
{
    extern __shared__ float sm[];
    float* xl   = sm;
    float* xr   = xl + N_*KHP_;
    float* wl   = xr + N_*KHP_;
    float* wr   = wl + F_*KH_;
    float* satt = wr + F_*KH_;
    float* sb   = satt + KH_;
    float* sx   = sb + KH_;
    float* se   = sx + N_*F_;
    int* ssrc = (int*)(se + E_*K_);
    int* sdst = ssrc + E_;
    int* soff = sdst + E_;
    int* seid = soff + (N_+1);

    int g = blockIdx.x;
    int tid = threadIdx.x;

    for (int i = tid; i < F_*KH_; i += 256) { wl[i] = Wl[i]; wr[i] = Wr[i]; }
    satt[tid] = att[tid];
    sb[tid] = bias[tid];
    for (int i = tid; i < N_*F_; i += 256) sx[i] = x[(size_t)g*N_*F_ + i];
    for (int i = tid; i < E_; i += 256) { ssrc[i] = ei[i]; sdst[i] = ei[E_+i]; seid[i] = g_ceid[i]; }
    for (int i = tid; i <= N_; i += 256) soff[i] = g_coff[i];
    __syncthreads();

    const int o = tid;
    for (int n = 0; n < N_; n++) {
        float al = 0.f, ar = 0.f;
        #pragma unroll
        for (int f = 0; f < F_; f++) {
            float xv = sx[n*F_ + f];
            al += xv * wl[f*KH_ + o];
            ar += xv * wr[f*KH_ + o];
        }
        xl[n*KHP_ + o] = al;
        xr[n*KHP_ + o] = ar;
    }
    __syncthreads();

    for (int idx = tid; idx < E_*K_; idx += 256) {
        int e = idx >> 2, k = idx & 3;
        const float* pl = xl + ssrc[e]*KHP_ + k*H_;
        const float* pr = xr + sdst[e]*KHP_ + k*H_;
        const float* pa = satt + k*H_;
        float acc = 0.f;
        #pragma unroll 8
        for (int h = 0; h < H_; h++) {
            float v = pl[h] + pr[h];
            v = v > 0.f ? v : NEG_SLOPE * v;
            acc += v * pa[h];
        }
        se[idx] = acc;
    }
    __syncthreads();

    for (int idx = tid; idx < N_*K_; idx += 256) {
        int n = idx >> 2, k = idx & 3;
        int a0 = soff[n], a1 = soff[n+1];
        float mx = -1e30f;
        for (int a = a0; a < a1; a++) mx = fmaxf(mx, se[seid[a]*K_ + k]);
        float s = 0.f;
        for (int a = a0; a < a1; a++) s += expf(se[seid[a]*K_ + k] - mx);
        float inv = 1.f / (s + 1e-16f);
        for (int a = a0; a < a1; a++) {
            int j = seid[a]*K_ + k;
            se[j] = expf(se[j] - mx) * inv;
        }
    }
    __syncthreads();

    int k = o >> 6;
    float* outp = g_h1 + (size_t)g*N_*KH_;
    for (int n = 0; n < N_; n++) {
        int a0 = soff[n], a1 = soff[n+1];
        float acc = 0.f;
        for (int a = a0; a < a1; a++) {
            int e = seid[a];
            acc += se[e*K_ + k] * xl[ssrc[e]*KHP_ + o];
        }
        outp[n*KH_ + o] = fmaxf(acc + sb[o], 0.f);
    }
}

// ---------------- GAT layer 2 (fused fp32, proven) ----------------------------
__global__ __launch_bounds__(256) void gat2_kernel(
    const int* __restrict__ ei,
    const float* __restrict__ Wl, const float* __restrict__ Wr,
    const float* __restrict__ att, const float* __restrict__ bias)
{
    extern __shared__ float sm[];
    float* sh_in = sm;
    float* xl    = sh_in + N_*KH_;
    float* xr    = xl + N_*KHP_;
    float* satt  = xr + N_*KHP_;
    float* sb    = satt + KH_;
    float* se    = sb + H_;
    int* ssrc = (int*)(se + E_*K_);
    int* sdst = ssrc + E_;
    int* soff = sdst + E_;
    int* seid = soff + (N_+1);

    int g = blockIdx.x;
    int tid = threadIdx.x;

    const float* h1p = g_h1 + (size_t)g*N_*KH_;
    for (int i = tid; i < N_*KH_; i += 256) sh_in[i] = h1p[i];
    satt[tid] = att[tid];
    if (tid < H_) sb[tid] = bias[tid];
    for (int i = tid; i < E_; i += 256) { ssrc[i] = ei[i]; sdst[i] = ei[E_+i]; seid[i] = g_ceid[i]; }
    for (int i = tid; i <= N_; i += 256) soff[i] = g_coff[i];
    __syncthreads();

    const int o = tid;
    {
        float acc[N_];
        #pragma unroll
        for (int n = 0; n < N_; n++) acc[n] = 0.f;
        #pragma unroll 2
        for (int i = 0; i < KH_; i++) {
            float w = Wl[i*KH_ + o];
            #pragma unroll
            for (int n = 0; n < N_; n++) acc[n] += sh_in[n*KH_ + i] * w;
        }
        #pragma unroll
        for (int n = 0; n < N_; n++) xl[n*KHP_ + o] = acc[n];
    }
    {
        float acc[N_];
        #pragma unroll
        for (int n = 0; n < N_; n++) acc[n] = 0.f;
        #pragma unroll 2
        for (int i = 0; i < KH_; i++) {
            float w = Wr[i*KH_ + o];
            #pragma unroll
            for (int n = 0; n < N_; n++) acc[n] += sh_in[n*KH_ + i] * w;
        }
        #pragma unroll
        for (int n = 0; n < N_; n++) xr[n*KHP_ + o] = acc[n];
    }
    __syncthreads();

    for (int idx = tid; idx < E_*K_; idx += 256) {
        int e = idx >> 2, k = idx & 3;
        const float* pl = xl + ssrc[e]*KHP_ + k*H_;
        const float* pr = xr + sdst[e]*KHP_ + k*H_;
        const float* pa = satt + k*H_;
        float acc = 0.f;
        #pragma unroll 8
        for (int h = 0; h < H_; h++) {
            float v = pl[h] + pr[h];
            v = v > 0.f ? v : NEG_SLOPE * v;
            acc += v * pa[h];
        }
        se[idx] = acc;
    }
    __syncthreads();

    for (int idx = tid; idx < N_*K_; idx += 256) {
        int n = idx >> 2, k = idx & 3;
        int a0 = soff[n], a1 = soff[n+1];
        float mx = -1e30f;
        for (int a = a0; a < a1; a++) mx = fmaxf(mx, se[seid[a]*K_ + k]);
        float s = 0.f;
        for (int a = a0; a < a1; a++) s += expf(se[seid[a]*K_ + k] - mx);
        float inv = 1.f / (s + 1e-16f);
        for (int a = a0; a < a1; a++) {
            int j = seid[a]*K_ + k;
            se[j] = expf(se[j] - mx) * inv;
        }
    }
    __syncthreads();

    for (int idx = tid; idx < N_*H_; idx += 256) {
        int n = idx >> 6, h = idx & 63;
        int a0 = soff[n], a1 = soff[n+1];
        float acc = 0.f;
        for (int a = a0; a < a1; a++) {
            int e = seid[a]; int s = ssrc[e];
            #pragma unroll
            for (int k2 = 0; k2 < K_; k2++)
                acc += se[e*K_ + k2] * xl[s*KHP_ + k2*H_ + h];
        }
        float v = acc * 0.25f + sb[h];
        g_seq[(size_t)g*NH_ + n*H_ + h] = fmaxf(v, 0.f);
    }
}

// ---------------- xw = seq @ W_ih^T + bias, tf32 3x via WMMA -------------------
// A = g_seq [1024 x 3072] row-major (ld 3072)
// B = W_ih  [2048 x 3072] row-major == col-major K x N with ld 3072
// C = g_xw  [1024 x 2048]
__global__ __launch_bounds__(128) void xw_wmma_kernel(
    const float* __restrict__ W_ih,
    const float* __restrict__ b_ih, const float* __restrict__ b_hh)
{
    const int warp = threadIdx.x >> 5, lane = threadIdx.x & 31;
    const int m0 = blockIdx.y*64 + (warp >> 1)*32;   // this warp's 32 rows
    const int n0 = blockIdx.x*64 + (warp & 1)*32;    // this warp's 32 cols

    wmma::fragment<wmma::accumulator,16,16,8,float> c[2][2];
    #pragma unroll
    for (int i = 0; i < 2; i++)
        #pragma unroll
        for (int j = 0; j < 2; j++) wmma::fill_fragment(c[i][j], 0.f);

    for (int k0 = 0; k0 < NH_; k0 += 8) {
        wmma::fragment<wmma::matrix_a,16,16,8,wmma::precision::tf32,wmma::row_major> ah[2], al[2];
        wmma::fragment<wmma::matrix_b,16,16,8,wmma::precision::tf32,wmma::col_major> bh[2], bl[2];
        #pragma unroll
        for (int i = 0; i < 2; i++) {
            wmma::load_matrix_sync(ah[i], g_seq + (size_t)(m0 + i*16)*NH_ + k0, NH_);
            #pragma unroll
            for (int e = 0; e < ah[i].num_elements; e++) {
                float v = ah[i].x[e];
                float hi = wmma::__float_to_tf32(v);
                al[i].x[e] = wmma::__float_to_tf32(v - hi);
                ah[i].x[e] = hi;
            }
            wmma::load_matrix_sync(bh[i], W_ih + (size_t)(n0 + i*16)*NH_ + k0, NH_);
            #pragma unroll
            for (int e = 0; e < bh[i].num_elements; e++) {
                float v = bh[i].x[e];
                float hi = wmma::__float_to_tf32(v);
                bl[i].x[e] = wmma::__float_to_tf32(v - hi);
                bh[i].x[e] = hi;
            }
        }
        #pragma unroll
        for (int i = 0; i < 2; i++)
            #pragma unroll
            for (int j = 0; j < 2; j++) {
                wmma::mma_sync(c[i][j], ah[i], bh[j], c[i][j]);   // hi*hi
                wmma::mma_sync(c[i][j], al[i], bh[j], c[i][j]);   // lo*hi
                wmma::mma_sync(c[i][j], ah[i], bl[j], c[i][j]);   // hi*lo
            }
    }

    // epilogue: stage through smem, add bias, vectorized store
    __shared__ float ctile[4][32][36];
    #pragma unroll
    for (int i = 0; i < 2; i++)
        #pragma unroll
        for (int j = 0; j < 2; j++)
            wmma::store_matrix_sync(&ctile[warp][i*16][j*16], c[i][j], 36, wmma::mem_row_major);
    __syncwarp();

    for (int q = lane; q < 256; q += 32) {
        int r = q >> 3, cq = (q & 7)*4;
        float4 v = *(const float4*)&ctile[warp][r][cq];
        int gr = m0 + r;
        int gc = n0 + cq;
        v.x += b_ih[gc+0] + b_hh[gc+0];
        v.y += b_ih[gc+1] + b_hh[gc+1];
        v.z += b_ih[gc+2] + b_hh[gc+2];
        v.w += b_ih[gc+3] + b_hh[gc+3];
        *(float4*)&g_xw[(size_t)gr*G4_ + gc] = v;
    }
}

// ---------------- persistent LSTM (exact R3 version, proven) ------------------
__device__ __forceinline__ float sigm(float x) { return 1.f / (1.f + expf(-x)); }

__device__ __forceinline__ void init_barrier()
{
    __syncthreads();
    if (threadIdx.x == 0) {
        unsigned my = g_gen;
        __threadfence();
        if (atomicAdd(&g_cnt, 1u) == LCTAS - 1) {
            atomicExch(&g_cnt, 0u);
            __threadfence();
            atomicAdd((unsigned*)&g_gen, 1u);
        } else {
            while (g_gen == my) { }
        }
    }
    __syncthreads();
}

__global__ __launch_bounds__(LTHR) void lstm_kernel(const float* __restrict__ W_hh)
{
    extern __shared__ float sm[];
    float* sw = sm;                      // 32 rows x WPAD
    float* sh = sw + 32*WPAD;            // B_*LH_ staged h

    int tid = threadIdx.x;
    int blk = blockIdx.x;
    int j0 = blk * JPC;

    for (int idx = tid; idx < 32*LH_; idx += LTHR) {
        int row = idx >> 9;
        int i = idx & 511;
        int gate = row >> 3, jj = row & 7;
        sw[row*WPAD + i] = W_hh[(size_t)(gate*LH_ + j0 + jj)*LH_ + i];
    }
    if (tid < T_/LCTAS) g_scnt[blk*(T_/LCTAS) + tid] = 0;
    for (int idx = tid; idx < B_*JPC; idx += LTHR) {
        int b = idx >> 3, jj = idx & 7;
        g_hbuf[0][b][j0 + jj] = 0.f;
    }
    __threadfence();
    init_barrier();

    const int b = tid >> 5;
    const int lane = tid & 31;
    const int gate = lane >> 3, jj = lane & 7;
    const int row = gate*8 + jj;
    const float4* wv = (const float4*)(sw + row*WPAD);
    const float* xp = g_xw + (size_t)(b*T_)*G4_ + gate*LH_ + j0 + jj;
    float c = 0.f;

    for (int t = 0; t < T_; t++) {
        int p = t & 1;
        float4 hstage[4];
        #pragma unroll
        for (int q = 0; q < 4; q++)
            hstage[q] = __ldcg(((const float4*)&g_hbuf[p][0][0]) + tid + q*LTHR);
        float xval = __ldcg(xp + (size_t)t*G4_);
        #pragma unroll
        for (int q = 0; q < 4; q++)
            ((float4*)sh)[tid + q*LTHR] = hstage[q];
        __syncthreads();

        const float4* hv = (const float4*)(sh + b*LH_);
        float4 a0 = make_float4(0.f,0.f,0.f,0.f);
        float4 a1 = make_float4(0.f,0.f,0.f,0.f);
        #pragma unroll 8
        for (int i = 0; i < LH_/8; i++) {
            float4 w0 = wv[2*i],   h0 = hv[2*i];
            float4 w1 = wv[2*i+1], h1 = hv[2*i+1];
            a0.x += w0.x*h0.x; a0.y += w0.y*h0.y; a0.z += w0.z*h0.z; a0.w += w0.w*h0.w;
            a1.x += w1.x*h1.x; a1.y += w1.y*h1.y; a1.z += w1.z*h1.z; a1.w += w1.w*h1.w;
        }
        float val = ((a0.x+a0.y)+(a0.z+a0.w)) + ((a1.x+a1.y)+(a1.z+a1.w)) + xval;

        float gi = __shfl_sync(0xffffffffu, val, jj);
        float gf = __shfl_sync(0xffffffffu, val, 8 + jj);
        float gg = __shfl_sync(0xffffffffu, val, 16 + jj);
        float go = __shfl_sync(0xffffffffu, val, 24 + jj);
        if (lane < 8) {
            c = sigm(gf)*c + sigm(gi)*tanhf(gg);
            float h = sigm(go)*tanhf(c);
            g_hbuf[p ^ 1][b][j0 + lane] = h;
        }
        __syncthreads();
        if (t < T_-1) {
            if (tid == 0) {
                __threadfence();
                atomicAdd(&g_scnt[t], 1u);
            }
            volatile unsigned* cp = &g_scnt[t];
            while (*cp < LCTAS) { }
            __threadfence();
        }
    }
}

// ---------------- final fc -----------------------------------------------------
__global__ void fc_kernel(const float* __restrict__ fc_w,
                          const float* __restrict__ fc_b,
                          float* __restrict__ out)
{
    int tid = threadIdx.x;
    if (tid < B_*C_) {
        int b = tid >> 3, c = tid & 7;
        const float* h = g_hbuf[0][b];
        const float* w = fc_w + c*LH_;
        float acc = 0.f;
        for (int j = 0; j < LH_; j++) acc += h[j] * w[j];
        out[b*C_ + c] = acc + fc_b[c];
    }
}

// ---------------- launch -------------------------------------------------------
extern "C" void kernel_launch(void* const* d_in, const int* in_sizes, int n_in,
                              void* d_out, int out_size)
{
    (void)in_sizes; (void)n_in; (void)out_size;
    const float* x    = (const float*)d_in[0];
    const int*   ei   = (const int*)d_in[1];
    const float* Wl1  = (const float*)d_in[2];
    const float* Wr1  = (const float*)d_in[3];
    const float* att1 = (const float*)d_in[4];
    const float* b1   = (const float*)d_in[5];
    const float* Wl2  = (const float*)d_in[6];
    const float* Wr2  = (const float*)d_in[7];
    const float* att2 = (const float*)d_in[8];
    const float* b2   = (const float*)d_in[9];
    const float* W_ih = (const float*)d_in[10];
    const float* W_hh = (const float*)d_in[11];
    const float* b_ih = (const float*)d_in[12];
    const float* b_hh = (const float*)d_in[13];
    const float* fc_w = (const float*)d_in[14];
    const float* fc_b = (const float*)d_in[15];
    float* out = (float*)d_out;

    const size_t sm1 = (size_t)(2*N_*KHP_ + 2*F_*KH_ + 2*KH_ + N_*F_ + E_*K_) * 4
                     + (size_t)(2*E_ + (N_+1) + E_) * 4;
    const size_t sm2 = (size_t)(N_*KH_ + 2*N_*KHP_ + KH_ + H_ + E_*K_) * 4
                     + (size_t)(2*E_ + (N_+1) + E_) * 4;
    const size_t sml = (size_t)(32*WPAD + B_*LH_) * 4;

    cudaFuncSetAttribute(gat1_kernel, cudaFuncAttributeMaxDynamicSharedMemorySize, (int)sm1);
    cudaFuncSetAttribute(gat2_kernel, cudaFuncAttributeMaxDynamicSharedMemorySize, (int)sm2);
    cudaFuncSetAttribute(lstm_kernel, cudaFuncAttributeMaxDynamicSharedMemorySize, (int)sml);

    build_csr_kernel<<<1, 64>>>(ei);
    gat1_kernel<<<G_, 256, sm1>>>(x, ei, Wl1, Wr1, att1, b1);
    gat2_kernel<<<G_, 256, sm2>>>(ei, Wl2, Wr2, att2, b2);
    xw_wmma_kernel<<<dim3(G4_/64, G_/64), 128>>>(W_ih, b_ih, b_hh);
    lstm_kernel<<<LCTAS, LTHR, sml>>>(W_hh);
    fc_kernel<<<1, 32>>>(fc_w, fc_b, out);
}

// round 10
// speedup vs baseline: 1.0973x; 1.0066x over previous
#include <cuda_runtime.h>
#include <math.h>
#include <mma.h>
using namespace nvcuda;

#define B_ 4
#define T_ 256
#define N_ 48
#define F_ 4
#define H_ 64
#define K_ 4
#define E_ 192
#define LH_ 512
#define C_ 8
#define G_ (B_*T_)     // 1024
#define KH_ (K_*H_)    // 256
#define KHP_ (KH_+1)
#define NH_ (N_*H_)    // 3072
#define G4_ (4*LH_)    // 2048
#define NEG_SLOPE 0.2f

#define LCTAS 64
#define LTHR 128
#define JPC 8
#define WPAD 516

// ---------------- scratch ----------------------------------------------------
__device__ float g_h1[G_*N_*KH_];
__device__ float g_seq[G_*NH_];
__device__ float g_xw[G_*G4_];
__device__ float g_hbuf[2][B_][LH_];
__device__ int   g_coff[N_+1];
__device__ int   g_ceid[E_];
__device__ unsigned g_cnt;
__device__ volatile unsigned g_gen;
__device__ unsigned g_scnt[T_];

// ---------------- deterministic CSR build ------------------------------------
__global__ void build_csr_kernel(const int* __restrict__ ei)
{
    __shared__ int sdst[E_];
    __shared__ int sdeg[N_];
    __shared__ int soff[N_+1];
    int tid = threadIdx.x;
    for (int e = tid; e < E_; e += blockDim.x) sdst[e] = ei[E_ + e];
    __syncthreads();
    for (int n = tid; n < N_; n += blockDim.x) {
        int d = 0;
        for (int e = 0; e < E_; e++) d += (sdst[e] == n);
        sdeg[n] = d;
    }
    __syncthreads();
    if (tid == 0) {
        int acc = 0;
        for (int n = 0; n < N_; n++) { soff[n] = acc; acc += sdeg[n]; }
        soff[N_] = acc;
    }
    __syncthreads();
    for (int n = tid; n < N_; n += blockDim.x) {
        int p = soff[n];
        for (int e = 0; e < E_; e++) if (sdst[e] == n) g_ceid[p++] = e;
    }
    for (int n = tid; n <= N_; n += blockDim.x) g_coff[n] = soff[n];
}

// ---------------- GAT layer 1 ------------------------------------------------
__global__ __launch_bounds__(256) void gat1_kernel(
    const float* __restrict__ x, const int* __restrict__ ei,
    const float* __restrict__ Wl, const float* __restrict__ Wr,
    const float* __restrict__ att, const float* __restrict__ bias)
{
    extern __shared__ float sm[];
    float* xl   = sm;
    float* xr   = xl + N_*KHP_;
    float* wl   = xr + N_*KHP_;
    float* wr   = wl + F_*KH_;
    float* satt = wr + F_*KH_;
    float* sb   = satt + KH_;
    float* sx   = sb + KH_;
    float* se   = sx + N_*F_;
    int* ssrc = (int*)(se + E_*K_);
    int* sdst = ssrc + E_;
    int* soff = sdst + E_;
    int* seid = soff + (N_+1);

    int g = blockIdx.x;
    int tid = threadIdx.x;

    for (int i = tid; i < F_*KH_; i += 256) { wl[i] = Wl[i]; wr[i] = Wr[i]; }
    satt[tid] = att[tid];
    sb[tid] = bias[tid];
    for (int i = tid; i < N_*F_; i += 256) sx[i] = x[(size_t)g*N_*F_ + i];
    for (int i = tid; i < E_; i += 256) { ssrc[i] = ei[i]; sdst[i] = ei[E_+i]; seid[i] = g_ceid[i]; }
    for (int i = tid; i <= N_; i += 256) soff[i] = g_coff[i];
    __syncthreads();

    const int o = tid;
    for (int n = 0; n < N_; n++) {
        float al = 0.f, ar = 0.f;
        #pragma unroll
        for (int f = 0; f < F_; f++) {
            float xv = sx[n*F_ + f];
            al += xv * wl[f*KH_ + o];
            ar += xv * wr[f*KH_ + o];
        }
        xl[n*KHP_ + o] = al;
        xr[n*KHP_ + o] = ar;
    }
    __syncthreads();

    for (int idx = tid; idx < E_*K_; idx += 256) {
        int e = idx >> 2, k = idx & 3;
        const float* pl = xl + ssrc[e]*KHP_ + k*H_;
        const float* pr = xr + sdst[e]*KHP_ + k*H_;
        const float* pa = satt + k*H_;
        float acc = 0.f;
        #pragma unroll 8
        for (int h = 0; h < H_; h++) {
            float v = pl[h] + pr[h];
            v = v > 0.f ? v : NEG_SLOPE * v;
            acc += v * pa[h];
        }
        se[idx] = acc;
    }
    __syncthreads();

    for (int idx = tid; idx < N_*K_; idx += 256) {
        int n = idx >> 2, k = idx & 3;
        int a0 = soff[n], a1 = soff[n+1];
        float mx = -1e30f;
        for (int a = a0; a < a1; a++) mx = fmaxf(mx, se[seid[a]*K_ + k]);
        float s = 0.f;
        for (int a = a0; a < a1; a++) s += expf(se[seid[a]*K_ + k] - mx);
        float inv = 1.f / (s + 1e-16f);
        for (int a = a0; a < a1; a++) {
            int j = seid[a]*K_ + k;
            se[j] = expf(se[j] - mx) * inv;
        }
    }
    __syncthreads();

    int k = o >> 6;
    float* outp = g_h1 + (size_t)g*N_*KH_;
    for (int n = 0; n < N_; n++) {
        int a0 = soff[n], a1 = soff[n+1];
        float acc = 0.f;
        for (int a = a0; a < a1; a++) {
            int e = seid[a];
            acc += se[e*K_ + k] * xl[ssrc[e]*KHP_ + o];
        }
        outp[n*KH_ + o] = fmaxf(acc + sb[o], 0.f);
    }
}

// ---------------- GAT layer 2 (fused fp32, proven) ----------------------------
__global__ __launch_bounds__(256) void gat2_kernel(
    const int* __restrict__ ei,
    const float* __restrict__ Wl, const float* __restrict__ Wr,
    const float* __restrict__ att, const float* __restrict__ bias)
{
    extern __shared__ float sm[];
    float* sh_in = sm;
    float* xl    = sh_in + N_*KH_;
    float* xr    = xl + N_*KHP_;
    float* satt  = xr + N_*KHP_;
    float* sb    = satt + KH_;
    float* se    = sb + H_;
    int* ssrc = (int*)(se + E_*K_);
    int* sdst = ssrc + E_;
    int* soff = sdst + E_;
    int* seid = soff + (N_+1);

    int g = blockIdx.x;
    int tid = threadIdx.x;

    const float* h1p = g_h1 + (size_t)g*N_*KH_;
    for (int i = tid; i < N_*KH_; i += 256) sh_in[i] = h1p[i];
    satt[tid] = att[tid];
    if (tid < H_) sb[tid] = bias[tid];
    for (int i = tid; i < E_; i += 256) { ssrc[i] = ei[i]; sdst[i] = ei[E_+i]; seid[i] = g_ceid[i]; }
    for (int i = tid; i <= N_; i += 256) soff[i] = g_coff[i];
    __syncthreads();

    const int o = tid;
    {
        float acc[N_];
        #pragma unroll
        for (int n = 0; n < N_; n++) acc[n] = 0.f;
        #pragma unroll 2
        for (int i = 0; i < KH_; i++) {
            float w = Wl[i*KH_ + o];
            #pragma unroll
            for (int n = 0; n < N_; n++) acc[n] += sh_in[n*KH_ + i] * w;
        }
        #pragma unroll
        for (int n = 0; n < N_; n++) xl[n*KHP_ + o] = acc[n];
    }
    {
        float acc[N_];
        #pragma unroll
        for (int n = 0; n < N_; n++) acc[n] = 0.f;
        #pragma unroll 2
        for (int i = 0; i < KH_; i++) {
            float w = Wr[i*KH_ + o];
            #pragma unroll
            for (int n = 0; n < N_; n++) acc[n] += sh_in[n*KH_ + i] * w;
        }
        #pragma unroll
        for (int n = 0; n < N_; n++) xr[n*KHP_ + o] = acc[n];
    }
    __syncthreads();

    for (int idx = tid; idx < E_*K_; idx += 256) {
        int e = idx >> 2, k = idx & 3;
        const float* pl = xl + ssrc[e]*KHP_ + k*H_;
        const float* pr = xr + sdst[e]*KHP_ + k*H_;
        const float* pa = satt + k*H_;
        float acc = 0.f;
        #pragma unroll 8
        for (int h = 0; h < H_; h++) {
            float v = pl[h] + pr[h];
            v = v > 0.f ? v : NEG_SLOPE * v;
            acc += v * pa[h];
        }
        se[idx] = acc;
    }
    __syncthreads();

    for (int idx = tid; idx < N_*K_; idx += 256) {
        int n = idx >> 2, k = idx & 3;
        int a0 = soff[n], a1 = soff[n+1];
        float mx = -1e30f;
        for (int a = a0; a < a1; a++) mx = fmaxf(mx, se[seid[a]*K_ + k]);
        float s = 0.f;
        for (int a = a0; a < a1; a++) s += expf(se[seid[a]*K_ + k] - mx);
        float inv = 1.f / (s + 1e-16f);
        for (int a = a0; a < a1; a++) {
            int j = seid[a]*K_ + k;
            se[j] = expf(se[j] - mx) * inv;
        }
    }
    __syncthreads();

    for (int idx = tid; idx < N_*H_; idx += 256) {
        int n = idx >> 6, h = idx & 63;
        int a0 = soff[n], a1 = soff[n+1];
        float acc = 0.f;
        for (int a = a0; a < a1; a++) {
            int e = seid[a]; int s = ssrc[e];
            #pragma unroll
            for (int k2 = 0; k2 < K_; k2++)
                acc += se[e*K_ + k2] * xl[s*KHP_ + k2*H_ + h];
        }
        float v = acc * 0.25f + sb[h];
        g_seq[(size_t)g*NH_ + n*H_ + h] = fmaxf(v, 0.f);
    }
}

// ---------------- xw = seq @ W_ih^T + bias, tf32 3x WMMA, smem-staged ---------
// A = g_seq [1024 x 3072] row-major; B = W_ih [2048 x 3072] row-major (= B^T op)
__global__ __launch_bounds__(128) void xw_wmma_kernel(
    const float* __restrict__ W_ih,
    const float* __restrict__ b_ih, const float* __restrict__ b_hh)
{
    __shared__ float smem[4608];         // As[64*36] | Bs[64*36]
    float* As = smem;
    float* Bs = smem + 2304;
    const int tid = threadIdx.x, warp = tid >> 5, lane = tid & 31;
    const int bm = blockIdx.y*64, bn = blockIdx.x*64;
    const int wm = (warp >> 1)*32, wn = (warp & 1)*32;

    wmma::fragment<wmma::accumulator,16,16,8,float> c[2][2];
    #pragma unroll
    for (int i = 0; i < 2; i++)
        #pragma unroll
        for (int j = 0; j < 2; j++) wmma::fill_fragment(c[i][j], 0.f);

    for (int k0 = 0; k0 < NH_; k0 += 32) {
        __syncthreads();
        #pragma unroll
        for (int i = 0; i < 4; i++) {
            int idx = tid + i*128;
            int m = idx >> 3, kq = (idx & 7)*4;
            *(float4*)&As[m*36 + kq] = *(const float4*)&g_seq[(size_t)(bm+m)*NH_ + k0 + kq];
            *(float4*)&Bs[m*36 + kq] = *(const float4*)&W_ih[(size_t)(bn+m)*NH_ + k0 + kq];
        }
        __syncthreads();

        #pragma unroll
        for (int ks = 0; ks < 32; ks += 8) {
            wmma::fragment<wmma::matrix_a,16,16,8,wmma::precision::tf32,wmma::row_major> ah[2], al[2];
            wmma::fragment<wmma::matrix_b,16,16,8,wmma::precision::tf32,wmma::col_major> bh[2], bl[2];
            #pragma unroll
            for (int i = 0; i < 2; i++) {
                wmma::load_matrix_sync(ah[i], &As[(wm + i*16)*36 + ks], 36);
                #pragma unroll
                for (int e = 0; e < ah[i].num_elements; e++) {
                    float v = ah[i].x[e];
                    float hi = wmma::__float_to_tf32(v);
                    al[i].x[e] = wmma::__float_to_tf32(v - hi);
                    ah[i].x[e] = hi;
                }
                wmma::load_matrix_sync(bh[i], &Bs[(wn + i*16)*36 + ks], 36);
                #pragma unroll
                for (int e = 0; e < bh[i].num_elements; e++) {
                    float v = bh[i].x[e];
                    float hi = wmma::__float_to_tf32(v);
                    bl[i].x[e] = wmma::__float_to_tf32(v - hi);
                    bh[i].x[e] = hi;
                }
            }
            #pragma unroll
            for (int i = 0; i < 2; i++)
                #pragma unroll
                for (int j = 0; j < 2; j++) {
                    wmma::mma_sync(c[i][j], ah[i], bh[j], c[i][j]);
                    wmma::mma_sync(c[i][j], al[i], bh[j], c[i][j]);
                    wmma::mma_sync(c[i][j], ah[i], bl[j], c[i][j]);
                }
        }
    }

    // epilogue: stage through smem (reuse), add bias, vectorized store
    __syncthreads();
    float* ct = smem + warp*1152;        // 32x36 per warp
    #pragma unroll
    for (int i = 0; i < 2; i++)
        #pragma unroll
        for (int j = 0; j < 2; j++)
            wmma::store_matrix_sync(&ct[(i*16)*36 + j*16], c[i][j], 36, wmma::mem_row_major);
    __syncwarp();
    for (int q = lane; q < 256; q += 32) {
        int r = q >> 3, cq = (q & 7)*4;
        float4 v = *(const float4*)&ct[r*36 + cq];
        int gr = bm + wm + r, gc = bn + wn + cq;
        v.x += b_ih[gc+0] + b_hh[gc+0];
        v.y += b_ih[gc+1] + b_hh[gc+1];
        v.z += b_ih[gc+2] + b_hh[gc+2];
        v.w += b_ih[gc+3] + b_hh[gc+3];
        *(float4*)&g_xw[(size_t)gr*G4_ + gc] = v;
    }
}

// ---------------- persistent LSTM (exact R3 version, proven) ------------------
__device__ __forceinline__ float sigm(float x) { return 1.f / (1.f + expf(-x)); }

__device__ __forceinline__ void init_barrier()
{
    __syncthreads();
    if (threadIdx.x == 0) {
        unsigned my = g_gen;
        __threadfence();
        if (atomicAdd(&g_cnt, 1u) == LCTAS - 1) {
            atomicExch(&g_cnt, 0u);
            __threadfence();
            atomicAdd((unsigned*)&g_gen, 1u);
        } else {
            while (g_gen == my) { }
        }
    }
    __syncthreads();
}

__global__ __launch_bounds__(LTHR) void lstm_kernel(const float* __restrict__ W_hh)
{
    extern __shared__ float sm[];
    float* sw = sm;                      // 32 rows x WPAD
    float* sh = sw + 32*WPAD;            // B_*LH_ staged h

    int tid = threadIdx.x;
    int blk = blockIdx.x;
    int j0 = blk * JPC;

    for (int idx = tid; idx < 32*LH_; idx += LTHR) {
        int row = idx >> 9;
        int i = idx & 511;
        int gate = row >> 3, jj = row & 7;
        sw[row*WPAD + i] = W_hh[(size_t)(gate*LH_ + j0 + jj)*LH_ + i];
    }
    if (tid < T_/LCTAS) g_scnt[blk*(T_/LCTAS) + tid] = 0;
    for (int idx = tid; idx < B_*JPC; idx += LTHR) {
        int b = idx >> 3, jj = idx & 7;
        g_hbuf[0][b][j0 + jj] = 0.f;
    }
    __threadfence();
    init_barrier();

    const int b = tid >> 5;
    const int lane = tid & 31;
    const int gate = lane >> 3, jj = lane & 7;
    const int row = gate*8 + jj;
    const float4* wv = (const float4*)(sw + row*WPAD);
    const float* xp = g_xw + (size_t)(b*T_)*G4_ + gate*LH_ + j0 + jj;
    float c = 0.f;

    for (int t = 0; t < T_; t++) {
        int p = t & 1;
        float4 hstage[4];
        #pragma unroll
        for (int q = 0; q < 4; q++)
            hstage[q] = __ldcg(((const float4*)&g_hbuf[p][0][0]) + tid + q*LTHR);
        float xval = __ldcg(xp + (size_t)t*G4_);
        #pragma unroll
        for (int q = 0; q < 4; q++)
            ((float4*)sh)[tid + q*LTHR] = hstage[q];
        __syncthreads();

        const float4* hv = (const float4*)(sh + b*LH_);
        float4 a0 = make_float4(0.f,0.f,0.f,0.f);
        float4 a1 = make_float4(0.f,0.f,0.f,0.f);
        #pragma unroll 8
        for (int i = 0; i < LH_/8; i++) {
            float4 w0 = wv[2*i],   h0 = hv[2*i];
            float4 w1 = wv[2*i+1], h1 = hv[2*i+1];
            a0.x += w0.x*h0.x; a0.y += w0.y*h0.y; a0.z += w0.z*h0.z; a0.w += w0.w*h0.w;
            a1.x += w1.x*h1.x; a1.y += w1.y*h1.y; a1.z += w1.z*h1.z; a1.w += w1.w*h1.w;
        }
        float val = ((a0.x+a0.y)+(a0.z+a0.w)) + ((a1.x+a1.y)+(a1.z+a1.w)) + xval;

        float gi = __shfl_sync(0xffffffffu, val, jj);
        float gf = __shfl_sync(0xffffffffu, val, 8 + jj);
        float gg = __shfl_sync(0xffffffffu, val, 16 + jj);
        float go = __shfl_sync(0xffffffffu, val, 24 + jj);
        if (lane < 8) {
            c = sigm(gf)*c + sigm(gi)*tanhf(gg);
            float h = sigm(go)*tanhf(c);
            g_hbuf[p ^ 1][b][j0 + lane] = h;
        }
        __syncthreads();
        if (t < T_-1) {
            if (tid == 0) {
                __threadfence();
                atomicAdd(&g_scnt[t], 1u);
            }
            volatile unsigned* cp = &g_scnt[t];
            while (*cp < LCTAS) { }
            __threadfence();
        }
    }
}

// ---------------- final fc -----------------------------------------------------
__global__ void fc_kernel(const float* __restrict__ fc_w,
                          const float* __restrict__ fc_b,
                          float* __restrict__ out)
{
    int tid = threadIdx.x;
    if (tid < B_*C_) {
        int b = tid >> 3, c = tid & 7;
        const float* h = g_hbuf[0][b];
        const float* w = fc_w + c*LH_;
        float acc = 0.f;
        for (int j = 0; j < LH_; j++) acc += h[j] * w[j];
        out[b*C_ + c] = acc + fc_b[c];
    }
}

// ---------------- launch -------------------------------------------------------
extern "C" void kernel_launch(void* const* d_in, const int* in_sizes, int n_in,
                              void* d_out, int out_size)
{
    (void)in_sizes; (void)n_in; (void)out_size;
    const float* x    = (const float*)d_in[0];
    const int*   ei   = (const int*)d_in[1];
    const float* Wl1  = (const float*)d_in[2];
    const float* Wr1  = (const float*)d_in[3];
    const float* att1 = (const float*)d_in[4];
    const float* b1   = (const float*)d_in[5];
    const float* Wl2  = (const float*)d_in[6];
    const float* Wr2  = (const float*)d_in[7];
    const float* att2 = (const float*)d_in[8];
    const float* b2   = (const float*)d_in[9];
    const float* W_ih = (const float*)d_in[10];
    const float* W_hh = (const float*)d_in[11];
    const float* b_ih = (const float*)d_in[12];
    const float* b_hh = (const float*)d_in[13];
    const float* fc_w = (const float*)d_in[14];
    const float* fc_b = (const float*)d_in[15];
    float* out = (float*)d_out;

    const size_t sm1 = (size_t)(2*N_*KHP_ + 2*F_*KH_ + 2*KH_ + N_*F_ + E_*K_) * 4
                     + (size_t)(2*E_ + (N_+1) + E_) * 4;
    const size_t sm2 = (size_t)(N_*KH_ + 2*N_*KHP_ + KH_ + H_ + E_*K_) * 4
                     + (size_t)(2*E_ + (N_+1) + E_) * 4;
    const size_t sml = (size_t)(32*WPAD + B_*LH_) * 4;

    cudaFuncSetAttribute(gat1_kernel, cudaFuncAttributeMaxDynamicSharedMemorySize, (int)sm1);
    cudaFuncSetAttribute(gat2_kernel, cudaFuncAttributeMaxDynamicSharedMemorySize, (int)sm2);
    cudaFuncSetAttribute(lstm_kernel, cudaFuncAttributeMaxDynamicSharedMemorySize, (int)sml);

    build_csr_kernel<<<1, 64>>>(ei);
    gat1_kernel<<<G_, 256, sm1>>>(x, ei, Wl1, Wr1, att1, b1);
    gat2_kernel<<<G_, 256, sm2>>>(ei, Wl2, Wr2, att2, b2);
    xw_wmma_kernel<<<dim3(G4_/64, G_/64), 128>>>(W_ih, b_ih, b_hh);
    lstm_kernel<<<LCTAS, LTHR, sml>>>(W_hh);
    fc_kernel<<<1, 32>>>(fc_w, fc_b, out);
}